// round 16
// baseline (speedup 1.0000x reference)
#include <cuda_runtime.h>
#include <math.h>
#include <stdint.h>

#define NB   8
#define NT   128
#define NS   400
#define NH   256
#define NVOC 50257
#define NBT  (NB * NT)
#define BMW  1572              // bitmap words per batch: ceil(50257/32)=1571, +1 pad (zeroed)
#define HSZ  1024              // dedup hash table slots (power of two)
#define NTOT 51463168u         // total floats = NBT*NVOC
#define TF4  1024u             // float4s per tile (16 KB)
#define NTILE 12565u           // ceil(NTOT*4 / 16384); last tile = 4096 B exactly
#define GRID 1036u             // persistent blocks (~7/SM)

// ---------------- scratch (__device__ globals; no allocation allowed) --------
__device__ float2   g_coeff[NBT];       // per (b,t): {p_gen, -(1-p)*lse}
__device__ float    g_corr[NBT * NS];   // per (b,t,head s): (1-p)*c_v  (heads only)
__device__ unsigned g_bm[NB * BMW];     // per-b bitmap of touched vocab ids
__device__ short    g_sidx[NB * NVOC];  // per-b map: vocab id -> head slot (valid where bit set)

// ---------------- block reductions: warp shuffle + 8-partial broadcast -------
__device__ __forceinline__ float block_sum_256(float v, float* red) {
    #pragma unroll
    for (int o = 16; o; o >>= 1) v += __shfl_xor_sync(0xffffffffu, v, o);
    if ((threadIdx.x & 31) == 0) red[threadIdx.x >> 5] = v;
    __syncthreads();
    float tot = red[0] + red[1] + red[2] + red[3] + red[4] + red[5] + red[6] + red[7];
    __syncthreads();
    return tot;
}
__device__ __forceinline__ float block_max_256(float v, float* red) {
    #pragma unroll
    for (int o = 16; o; o >>= 1) v = fmaxf(v, __shfl_xor_sync(0xffffffffu, v, o));
    if ((threadIdx.x & 31) == 0) red[threadIdx.x >> 5] = v;
    __syncthreads();
    float m = fmaxf(fmaxf(fmaxf(red[0], red[1]), fmaxf(red[2], red[3])),
                    fmaxf(fmaxf(red[4], red[5]), fmaxf(red[6], red[7])));
    __syncthreads();
    return m;
}

// ---------------- kernel 1: fused dedup + p_gen + grouped-sum + lse ----------
__global__ __launch_bounds__(256)
void rowstats_kernel(const int*   __restrict__ tokens,
                     const float* __restrict__ ctx,
                     const float* __restrict__ din,
                     const float* __restrict__ dout,
                     const float* __restrict__ attn,
                     const float* __restrict__ Wc, const float* __restrict__ bc,
                     const float* __restrict__ Wo, const float* __restrict__ bo,
                     const float* __restrict__ Wi, const float* __restrict__ bi) {
    const int bt  = blockIdx.x;
    const int b   = bt >> 7;            // bt / NT
    const int tid = threadIdx.x;

    __shared__ float red[8];
    __shared__ float c_sm[NS];
    __shared__ int   hkey[HSZ];
    __shared__ int   hrep[HSZ];
    __shared__ int   cnt;

    #pragma unroll
    for (int i = tid; i < HSZ; i += 256) { hkey[i] = -1; hrep[i] = 0x7fffffff; }
    c_sm[tid] = 0.0f;
    if (tid < NS - 256) c_sm[tid + 256] = 0.0f;
    if (tid == 0) cnt = 0;
    __syncthreads();

    // --- build: insert this batch's tokens (slots tid and tid+256) ---
    const int tok0 = tokens[b * NS + tid];
    int tok1 = -1;
    {
        unsigned h = ((unsigned)tok0 * 2654435761u) & (HSZ - 1u);
        for (;;) {
            const int old = atomicCAS(&hkey[h], -1, tok0);
            if (old == -1 || old == tok0) break;
            h = (h + 1u) & (HSZ - 1u);
        }
        atomicMin(&hrep[h], tid);
    }
    if (tid < NS - 256) {
        tok1 = tokens[b * NS + tid + 256];
        unsigned h = ((unsigned)tok1 * 2654435761u) & (HSZ - 1u);
        for (;;) {
            const int old = atomicCAS(&hkey[h], -1, tok1);
            if (old == -1 || old == tok1) break;
            h = (h + 1u) & (HSZ - 1u);
        }
        atomicMin(&hrep[h], tid + 256);
    }

    // --- p_gen partial while the table settles ---
    const int base = bt * NH + tid;
    float partial = ctx[base]  * Wc[tid]
                  + dout[base] * Wo[tid]
                  + din[base]  * Wi[tid];
    __syncthreads();

    // --- probe: canonical head per slot (plain reads; table is final) ---
    unsigned hh = ((unsigned)tok0 * 2654435761u) & (HSZ - 1u);
    while (hkey[hh] != tok0) hh = (hh + 1u) & (HSZ - 1u);
    const int h0 = hrep[hh];
    int h1 = -1;
    if (tid < NS - 256) {
        unsigned h = ((unsigned)tok1 * 2654435761u) & (HSZ - 1u);
        while (hkey[h] != tok1) h = (h + 1u) & (HSZ - 1u);
        h1 = hrep[h];
    }

    const float z = block_sum_256(partial, red) + bc[0] + bo[0] + bi[0];
    const float p = 1.0f / (1.0f + expf(-z));
    const float q = 1.0f - p;

    // --- group attn values by canonical head ---
    atomicAdd(&c_sm[h0], attn[bt * NS + tid]);
    if (tid < NS - 256) atomicAdd(&c_sm[h1], attn[bt * NS + tid + 256]);
    __syncthreads();

    const bool head0 = (h0 == tid);
    const bool head1 = (h1 == tid + 256);
    const float c0 = head0 ? c_sm[tid]       : 0.0f;
    const float c1 = head1 ? c_sm[tid + 256] : 0.0f;
    if (head0) atomicAdd(&cnt, 1);
    if (head1) atomicAdd(&cnt, 1);

    // --- max over row (implicit zeros make 0 a valid floor; c >= 0 anyway) ---
    float m = 0.0f;
    if (head0) m = fmaxf(m, c0);
    if (head1) m = fmaxf(m, c1);
    m = block_max_256(m, red);

    // --- sumexp over heads + (V - n) zeros ---
    float se = 0.0f;
    if (head0) se += expf(c0 - m);
    if (head1) se += expf(c1 - m);
    se = block_sum_256(se, red);   // cnt's atomicAdds are pre-barrier: visible after

    if (tid == 0) {
        const float total = se + (float)(NVOC - cnt) * expf(-m);
        const float lse = m + logf(total);
        g_coeff[bt] = make_float2(p, -q * lse);
    }

    // --- correction values for fused-mix lookup ---
    if (head0) g_corr[bt * NS + tid]       = q * c0;
    if (head1) g_corr[bt * NS + tid + 256] = q * c1;

    // --- designated block per batch publishes bitmap + slot map ---
    if ((bt & (NT - 1)) == 0) {
        #pragma unroll
        for (int i = tid; i < BMW; i += 256) g_bm[b * BMW + i] = 0u;
        __syncthreads();
        if (head0) {
            atomicOr(&g_bm[b * BMW + ((unsigned)tok0 >> 5)], 1u << (tok0 & 31));
            g_sidx[b * NVOC + tok0] = (short)tid;
        }
        if (head1) {
            atomicOr(&g_bm[b * BMW + ((unsigned)tok1 >> 5)], 1u << (tok1 & 31));
            g_sidx[b * NVOC + tok1] = (short)(tid + 256);
        }
    }
}

// ---------------- TMA / mbarrier helpers -------------------------------------
__device__ __forceinline__ void mbar_init(unsigned mb, unsigned cnt) {
    asm volatile("mbarrier.init.shared.b64 [%0], %1;" :: "r"(mb), "r"(cnt) : "memory");
}
__device__ __forceinline__ void tma_fill(unsigned smem, const float* gsrc,
                                         unsigned bytes, unsigned mb) {
    asm volatile("mbarrier.arrive.expect_tx.shared.b64 _, [%0], %1;"
                 :: "r"(mb), "r"(bytes) : "memory");
    asm volatile("cp.async.bulk.shared::cluster.global.mbarrier::complete_tx::bytes "
                 "[%0], [%1], %2, [%3];"
                 :: "r"(smem), "l"(gsrc), "r"(bytes), "r"(mb) : "memory");
}
__device__ __forceinline__ void mbar_wait(unsigned mb, unsigned parity) {
    unsigned done;
    asm volatile(
        "{\n\t.reg .pred p;\n\t"
        "mbarrier.try_wait.parity.acquire.cta.shared::cta.b64 p, [%1], %2;\n\t"
        "selp.b32 %0, 1, 0, p;\n\t}"
        : "=r"(done) : "r"(mb), "r"(parity) : "memory");
    if (!done) {
        asm volatile(
            "{\n\t.reg .pred P1;\n\t"
            "WL_%=:\n\t"
            "mbarrier.try_wait.parity.acquire.cta.shared::cta.b64 P1, [%0], %1, 0x989680;\n\t"
            "@P1 bra.uni WD_%=;\n\t"
            "bra.uni WL_%=;\n\t"
            "WD_%=:\n\t}"
            :: "r"(mb), "r"(parity) : "memory");
    }
}

// ---------------- kernel 2: persistent double-buffered TMA mix ---------------
// 1036 persistent blocks; each loops over ~12 tiles of 16 KB with a 2-stage
// smem pipeline: TMA fill of tile k+1 overlaps compute+store of tile k.
// PDL: first tile's fill (input-only) is issued BEFORE the grid dependency
// sync, overlapping rowstats' tail and the launch gap.
__global__ __launch_bounds__(256)
void mix_kernel(const float* __restrict__ vocab, float* __restrict__ out) {
    __shared__ __align__(128) float4 s4[2][TF4];     // 2 x 16 KB stages
    __shared__ __align__(8) uint64_t mbar[2];

    const unsigned tid = threadIdx.x;
    const unsigned bid = blockIdx.x;
    const unsigned sd[2] = { (unsigned)__cvta_generic_to_shared(&s4[0][0]),
                             (unsigned)__cvta_generic_to_shared(&s4[1][0]) };
    const unsigned mb[2] = { (unsigned)__cvta_generic_to_shared(&mbar[0]),
                             (unsigned)__cvta_generic_to_shared(&mbar[1]) };

    if (tid == 0) { mbar_init(mb[0], 1); mbar_init(mb[1], 1); }
    __syncthreads();

    // prologue: prefetch tile0 (pure input read — legal before the dep-sync)
    if (tid == 0) {
        const unsigned by0 = (bid == NTILE - 1u) ? 4096u : 16384u;
        tma_fill(sd[0], vocab + bid * 4096u, by0, mb[0]);
    }

    cudaGridDependencySynchronize();   // rowstats outputs now visible

    unsigned k = 0;
    for (unsigned tile = bid; tile < NTILE; tile += GRID, ++k) {
        const unsigned s = k & 1u;
        const unsigned bytes = (tile == NTILE - 1u) ? 4096u : 16384u;

        // prefetch next tile into the other stage
        const unsigned nt = tile + GRID;
        if (tid == 0 && nt < NTILE) {
            // drain the bulk store that last read that stage's smem
            asm volatile("cp.async.bulk.wait_group.read 0;" ::: "memory");
            const unsigned nby = (nt == NTILE - 1u) ? 4096u : 16384u;
            tma_fill(sd[s ^ 1u], vocab + nt * 4096u, nby, mb[s ^ 1u]);
        }

        // wait for current tile
        mbar_wait(mb[s], (k >> 1) & 1u);

        // ---- compute in place: up to 4 float4s per thread ----
        const unsigned base_f = tile * 4096u;
        #pragma unroll
        for (int j = 0; j < 4; ++j) {
            const unsigned i4l = tid + (unsigned)j * 256u;
            if (i4l * 16u >= bytes) break;
            const float4 v = s4[s][i4l];
            const unsigned e   = base_f + i4l * 4u;
            const unsigned bt0 = e / (unsigned)NVOC;
            const unsigned rem = e - bt0 * (unsigned)NVOC;

            float4 o;
            if (rem <= (unsigned)(NVOC - 4)) {
                const float2 cf = g_coeff[bt0];
                o.x = fmaf(v.x, cf.x, cf.y);
                o.y = fmaf(v.y, cf.x, cf.y);
                o.z = fmaf(v.z, cf.x, cf.y);
                o.w = fmaf(v.w, cf.x, cf.y);

                const unsigned b = bt0 >> 7;
                const unsigned* __restrict__ bmp = g_bm + b * BMW;
                const unsigned w0 = rem >> 5;
                const unsigned bits =
                    __funnelshift_r(bmp[w0], bmp[w0 + 1], rem & 31u) & 15u;
                if (bits) {   // rare (~0.8% of float4s)
                    const short* __restrict__ sx   = g_sidx + b * NVOC;
                    const float* __restrict__ corr = g_corr + bt0 * NS;
                    if (bits & 1u) o.x += corr[sx[rem + 0u]];
                    if (bits & 2u) o.y += corr[sx[rem + 1u]];
                    if (bits & 4u) o.z += corr[sx[rem + 2u]];
                    if (bits & 8u) o.w += corr[sx[rem + 3u]];
                }
            } else {
                // float4 straddles a row boundary (V odd): general path (rare)
                float vv[4] = {v.x, v.y, v.z, v.w};
                float oo[4];
                #pragma unroll
                for (int i = 0; i < 4; ++i) {
                    const unsigned g   = e + (unsigned)i;
                    const unsigned bte = g / (unsigned)NVOC;
                    const unsigned r   = g - bte * (unsigned)NVOC;
                    const unsigned b   = bte >> 7;
                    const float2 c = g_coeff[bte];
                    float val = fmaf(vv[i], c.x, c.y);
                    if ((g_bm[b * BMW + (r >> 5)] >> (r & 31u)) & 1u)
                        val += g_corr[bte * NS + g_sidx[b * NVOC + r]];
                    oo[i] = val;
                }
                o.x = oo[0]; o.y = oo[1]; o.z = oo[2]; o.w = oo[3];
            }
            s4[s][i4l] = o;
        }
        __syncthreads();

        // ---- bulk store smem -> global ----
        if (tid == 0) {
            asm volatile("fence.proxy.async.shared::cta;" ::: "memory");
            asm volatile("cp.async.bulk.global.shared::cta.bulk_group [%0], [%1], %2;"
                         :: "l"(out + base_f), "r"(sd[s]), "r"(bytes) : "memory");
            asm volatile("cp.async.bulk.commit_group;" ::: "memory");
        }
    }

    // drain outstanding stores before exit
    if (tid == 0) asm volatile("cp.async.bulk.wait_group 0;" ::: "memory");
}

// ---------------- launch ------------------------------------------------------
extern "C" void kernel_launch(void* const* d_in, const int* in_sizes, int n_in,
                              void* d_out, int out_size) {
    const int*   tokens = (const int*)  d_in[0];   // [B, S]
    const float* ctx    = (const float*)d_in[1];   // [B, T, H]
    const float* din    = (const float*)d_in[2];   // [B, T, H]
    const float* dout   = (const float*)d_in[3];   // [B, T, H]
    const float* vocab  = (const float*)d_in[4];   // [B, T, V]
    const float* attn   = (const float*)d_in[5];   // [B, T, S]
    // d_in[6] = encoder_outputs (unused by reference)
    const float* Wc = (const float*)d_in[7];
    const float* bc = (const float*)d_in[8];
    const float* Wo = (const float*)d_in[9];
    const float* bo = (const float*)d_in[10];
    const float* Wi = (const float*)d_in[11];
    const float* bi = (const float*)d_in[12];
    float* out = (float*)d_out;

    rowstats_kernel<<<NBT, 256>>>(tokens, ctx, din, dout, attn,
                                  Wc, bc, Wo, bo, Wi, bi);

    // mix with PDL (programmatic stream serialization) so its TMA prologue
    // overlaps rowstats' tail; fall back to a plain launch if unsupported.
    cudaLaunchConfig_t cfg = {};
    cfg.gridDim  = dim3(GRID);
    cfg.blockDim = dim3(256);
    cfg.dynamicSmemBytes = 0;
    cfg.stream = 0;
    cudaLaunchAttribute at[1];
    at[0].id = cudaLaunchAttributeProgrammaticStreamSerialization;
    at[0].val.programmaticStreamSerializationAllowed = 1;
    cfg.attrs = at;
    cfg.numAttrs = 1;
    if (cudaLaunchKernelEx(&cfg, mix_kernel, vocab, out) != cudaSuccess) {
        mix_kernel<<<GRID, 256>>>(vocab, out);
    }
}